// round 12
// baseline (speedup 1.0000x reference)
#include <cuda_runtime.h>
#include <cuda_fp16.h>
#include <cstdint>
#include <math.h>

// Problem dims (fixed for this dataset)
#define NATOMS 20000
#define NEDGES 250000
#define DE 512
#define DA 256
#define DR 16

#define INV_SQRT2 0.70710678118654752440f

// fp16 k-permutation within each 16-element block:
// thread c's m16n8k16 fragment k's {2c,2c+1,2c+8,2c+9} land at {4c..4c+3}
__host__ __device__ __forceinline__ int kp16(int k) {
    int b = k & 15;
    return (k & ~15) | (b & 1) | (((b >> 1) & 3) << 2) | (((b >> 3) & 1) << 1);
}

// ---------------- scratch (device globals; no allocs allowed) ----------------
__device__ int    g_counts[NATOMS];          // zero at load; scan re-zeroes each pass
__device__ int    g_offsets[NATOMS + 1];
__device__ int    g_cursor[NATOMS];
__device__ int    g_sorted[NEDGES];
__device__ __half g_xbig[(size_t)NATOMS * DE];  // aggregated [A, De], fp16 kp-permuted
__device__ __half g_xa[(size_t)NATOMS * DA];    // atom features (fp16, kp-permuted)
__device__ __half g_ya[(size_t)NATOMS * DA];    // MLP intermediate (fp16, kp-permuted)
// transposed+fp16+kp-permuted weights: W_in^T [256,512] then 3x(W1^T,W2^T) [256,256]
__device__ __half g_wt[DA * DE + 6 * DA * DA];

// ---------------- helpers ----------------
__device__ __forceinline__ uint32_t smem_u32(const void* p) {
    uint32_t a;
    asm("{ .reg .u64 t; cvta.to.shared.u64 t, %1; cvt.u32.u64 %0, t; }" : "=r"(a) : "l"(p));
    return a;
}
__device__ __forceinline__ float silu(float x) { return x / (1.0f + __expf(-x)); }
__device__ __forceinline__ float tf32_rna(float x) {
    float y;
    asm("cvt.rna.tf32.f32 %0, %1;" : "=f"(y) : "f"(x));
    return y;
}

__device__ __forceinline__ void cp_async16(uint32_t dst, const void* src, int pred) {
    asm volatile("cp.async.cg.shared.global [%0], [%1], 16, %2;"
                 :: "r"(dst), "l"(src), "r"(pred ? 16 : 0) : "memory");
}
__device__ __forceinline__ void cp_commit() {
    asm volatile("cp.async.commit_group;" ::: "memory");
}
__device__ __forceinline__ void cp_wait0() {
    asm volatile("cp.async.wait_group 0;" ::: "memory");
}
__device__ __forceinline__ void cp_wait1() {
    asm volatile("cp.async.wait_group 1;" ::: "memory");
}
__device__ __forceinline__ void cp_wait2() {
    asm volatile("cp.async.wait_group 2;" ::: "memory");
}

// ---------------- counting sort of edges by atom ----------------
// hist also zero-fills g_xbig (0-edge atoms must read as zero)
__global__ void hist_kernel(const int* __restrict__ idx, int E, int A) {
    int i = blockIdx.x * blockDim.x + threadIdx.x;
    if (i < E) atomicAdd(&g_counts[idx[i]], 1);
    int total = A * DE / 8;   // uint4 = 8 halfs
    int nt = gridDim.x * blockDim.x;
    uint4 z = make_uint4(0u, 0u, 0u, 0u);
    uint4* px = reinterpret_cast<uint4*>(g_xbig);
    for (int j = i; j < total; j += nt) px[j] = z;
}
__global__ void scan_kernel(int A, int E) {
    __shared__ int sums[1024];
    int tid = threadIdx.x;
    int per = (A + 1023) / 1024;
    int start = tid * per;
    int end = min(start + per, A);
    int s = 0;
    for (int i = start; i < end; i++) s += g_counts[i];
    sums[tid] = s;
    __syncthreads();
    for (int off = 1; off < 1024; off <<= 1) {
        int v = 0;
        if (tid >= off) v = sums[tid - off];
        __syncthreads();
        sums[tid] += v;
        __syncthreads();
    }
    int run = (tid == 0) ? 0 : sums[tid - 1];
    for (int i = start; i < end; i++) {
        g_offsets[i] = run;
        g_cursor[i]  = run;
        run += g_counts[i];
        g_counts[i] = 0;
    }
    if (tid == 0) g_offsets[A] = E;
}
__global__ void scatter_kernel(const int* __restrict__ idx, int E) {
    int i = blockIdx.x * blockDim.x + threadIdx.x;
    if (i < E) {
        int p = atomicAdd(&g_cursor[idx[i]], 1);
        g_sorted[p] = i;
    }
}

// ---------------- edge-parallel aggregation with tf32-mma rbf projection ----------------
// Per 16-edge sub-tile: BS[16,512] = br_tile @ W_rbf via mma.m16n8k8.tf32 (W_rbf B-frags
// register-resident). Consume: acc[col] += m[e,col] * BS[e,col]; flush per atom (fp16,
// kp-permuted). Atom-exclusive block ownership -> no atomics.
#define AGG_TILE 64
#define AGG_SUB 16
#define AGG_BLOCKS 740
#define BS_STRIDE 520     // floats per BS row (512 + 8 pad)

__global__ __launch_bounds__(128, 5)
void aggregate_kernel(const float* __restrict__ m,
                      const float* __restrict__ br,
                      const float* __restrict__ Wrbf,
                      const int* __restrict__ idx, int E, int A) {
    __shared__ float s_bs[AGG_SUB * BS_STRIDE];   // 33280 B
    __shared__ float s_br[AGG_TILE][16];
    __shared__ int   s_e[AGG_TILE];
    __shared__ int   s_atom[AGG_TILE];
    __shared__ int   s_ab[2];

    const int tid  = threadIdx.x;
    const int lane = tid & 31;
    const int wid  = tid >> 5;          // 0..3
    const int r    = lane >> 2;         // 0..7
    const int c    = lane & 3;          // 0..3
    const int wbase = wid * 128;        // this warp's 128 columns

    // Preload W_rbf B-fragments (tf32) for this warp's 16 n-tiles x 2 k-chunks.
    // B[n=r][k=kq*8+{c,c+4}] with n = global col = wbase + j*8 + r.
    uint32_t bw[16][2][2];
#pragma unroll
    for (int j = 0; j < 16; j++) {
#pragma unroll
        for (int kq = 0; kq < 2; kq++) {
            int col = wbase + j * 8 + r;
            bw[j][kq][0] = __float_as_uint(tf32_rna(Wrbf[(kq * 8 + c) * DE + col]));
            bw[j][kq][1] = __float_as_uint(tf32_rna(Wrbf[(kq * 8 + c + 4) * DE + col]));
        }
    }

    const int c0 = tid * 4;             // consume columns 4t..4t+3
    const int P01 = kp16(c0);           // fp16 store slot of cols {c0, c0+1}
    const int P23 = kp16(c0 + 2);

    const int epb = (E + gridDim.x - 1) / gridDim.x;
    if (tid < 2) {
        int target = min((int)(blockIdx.x + tid) * epb, E);
        int lo = 0, hi = A;
        while (lo < hi) {
            int mid = (lo + hi) >> 1;
            if (g_offsets[mid] >= target) hi = mid; else lo = mid + 1;
        }
        s_ab[tid] = lo;
    }
    __syncthreads();
    const int a_beg = s_ab[0], a_end = s_ab[1];
    if (a_beg >= a_end) return;
    const int j0 = g_offsets[a_beg];
    const int j1 = g_offsets[a_end];

    float4 acc = make_float4(0.f, 0.f, 0.f, 0.f);
    int cur_atom = -1;

    auto flush = [&](int a) {
        __half* p = g_xbig + (size_t)a * DE;
        *reinterpret_cast<__half2*>(p + P01) = __floats2half2_rn(acc.x, acc.y);
        *reinterpret_cast<__half2*>(p + P23) = __floats2half2_rn(acc.z, acc.w);
    };

    for (int t0 = j0; t0 < j1; t0 += AGG_TILE) {
        const int n = min(AGG_TILE, j1 - t0);
        __syncthreads();
        {   // stage basis rows (tf32-rounded) + edge ids + atom ids: 2 threads/edge
            int el = tid >> 1;
            int half_ = tid & 1;
            if (el < n) {
                int e = g_sorted[t0 + el];
                if (half_ == 0) { s_e[el] = e; s_atom[el] = idx[e]; }
                const float* bp = br + (size_t)e * DR + half_ * 8;
#pragma unroll
                for (int q = 0; q < 8; q++)
                    s_br[el][half_ * 8 + q] = tf32_rna(bp[q]);
            }
        }
        __syncthreads();

        for (int st = 0; st < AGG_TILE / AGG_SUB; st++) {
            const int sb = st * AGG_SUB;             // sub-tile base (local)
            if (sb >= n) break;
            const int n_sub = min(AGG_SUB, n - sb);

            // ---- mma phase: BS[0..15][wbase..wbase+127] ----
            uint32_t a0[2], a1[2], a2[2], a3[2];
#pragma unroll
            for (int kq = 0; kq < 2; kq++) {
                a0[kq] = __float_as_uint(s_br[sb + r][kq * 8 + c]);
                a1[kq] = __float_as_uint(s_br[sb + 8 + r][kq * 8 + c]);
                a2[kq] = __float_as_uint(s_br[sb + r][kq * 8 + c + 4]);
                a3[kq] = __float_as_uint(s_br[sb + 8 + r][kq * 8 + c + 4]);
            }
#pragma unroll
            for (int j = 0; j < 16; j++) {
                float d0 = 0.f, d1 = 0.f, d2 = 0.f, d3 = 0.f;
#pragma unroll
                for (int kq = 0; kq < 2; kq++) {
                    asm volatile(
                        "mma.sync.aligned.m16n8k8.row.col.f32.tf32.tf32.f32 "
                        "{%0,%1,%2,%3}, {%4,%5,%6,%7}, {%8,%9}, {%0,%1,%2,%3};"
                        : "+f"(d0), "+f"(d1), "+f"(d2), "+f"(d3)
                        : "r"(a0[kq]), "r"(a1[kq]), "r"(a2[kq]), "r"(a3[kq]),
                          "r"(bw[j][kq][0]), "r"(bw[j][kq][1]));
                }
                int colb = wbase + j * 8 + 2 * c;
                *reinterpret_cast<float2*>(&s_bs[r * BS_STRIDE + colb]) =
                    make_float2(d0, d1);
                *reinterpret_cast<float2*>(&s_bs[(r + 8) * BS_STRIDE + colb]) =
                    make_float2(d2, d3);
            }
            __syncwarp();   // warp's own STS -> LDS (cols match warp-local threads)

            // ---- consume: acc += m[e, c0..c0+3] * BS[e_local, c0..c0+3] ----
            float4 mv = *reinterpret_cast<const float4*>(
                m + (size_t)s_e[sb] * DE + c0);
            for (int i = 0; i < n_sub; i++) {
                float4 mnext = mv;
                int gi = sb + i;
                if (gi + 1 < n)
                    mnext = *reinterpret_cast<const float4*>(
                        m + (size_t)s_e[gi + 1] * DE + c0);

                int a = s_atom[gi];
                if (a != cur_atom) {
                    if (cur_atom >= 0) flush(cur_atom);
                    cur_atom = a;
                    acc = make_float4(0.f, 0.f, 0.f, 0.f);
                }
                float4 bs = *reinterpret_cast<const float4*>(
                    &s_bs[i * BS_STRIDE + c0]);
                acc.x = fmaf(mv.x, bs.x, acc.x);
                acc.y = fmaf(mv.y, bs.y, acc.y);
                acc.z = fmaf(mv.z, bs.z, acc.z);
                acc.w = fmaf(mv.w, bs.w, acc.w);
                mv = mnext;
            }
            __syncwarp();   // all lanes done reading s_bs before next mma overwrites
        }
    }
    if (cur_atom >= 0) flush(cur_atom);
}

// ---------------- all-weights transpose + fp16 convert + kp-permute ----------------
__global__ void transpose_all_kernel(const float* __restrict__ Win,
                                     const float* __restrict__ W1,
                                     const float* __restrict__ W2,
                                     __half* __restrict__ wt, int nh) {
    int total = DE * DA + 2 * nh * DA * DA;
    for (int i = blockIdx.x * blockDim.x + threadIdx.x; i < total;
         i += gridDim.x * blockDim.x) {
        const float* src;
        __half* dst;
        int K, rem;
        if (i < DE * DA) {
            src = Win; dst = wt; K = DE; rem = i;
        } else {
            int j = i - DE * DA;
            int t = j / (DA * DA);
            rem = j % (DA * DA);
            src = ((t & 1) == 0 ? W1 : W2) + (size_t)(t >> 1) * DA * DA;
            dst = wt + DE * DA + (size_t)t * DA * DA;
            K = DA;
        }
        int k = rem / DA, n = rem % DA;
        dst[(size_t)n * K + kp16(k)] = __float2half_rn(src[rem]);
    }
}

// ---------------- mma.sync fp16 GEMM: 64x64 tile, 256 thr, 4 CTAs/SM, 4-stage ----------------
// mode 0: out = silu(A @ W^T)      mode 1: out = (res + silu(A @ W^T)) * INV_SQRT2
// outf != nullptr: final fp32 plain store; else fp16 kp-permuted store to outh.
#define BK 32                // fp16 elements of K per stage
#define RSW 24               // b32 words per smem row (48 halfs = 96B; conflict-free)
#define A_WORDS (64 * RSW)
#define B_WORDS (64 * RSW)
#define BUF_WORDS (A_WORDS + B_WORDS)
#define STAGES 4
#define GEMM_SMEM (STAGES * BUF_WORDS * 4)   // 49152 B

__global__ __launch_bounds__(256, 4)
void gemm_mma_kernel(const __half* __restrict__ Ain, const __half* __restrict__ Wt,
                     const __half* __restrict__ res, __half* __restrict__ outh,
                     float* __restrict__ outf, int M, int K, int mode) {
    extern __shared__ uint32_t smw[];
    const uint32_t sbase = smem_u32(smw);

    const int tid = threadIdx.x;
    const int lane = tid & 31;
    const int wid = tid >> 5;            // 0..7
    const int warp_m = wid & 3;          // 4 x 16 rows
    const int warp_n = wid >> 2;         // 2 x 32 cols
    const int bm = blockIdx.x * 64;
    const int bn = blockIdx.y * 64;
    const int r = lane >> 2;
    const int c = lane & 3;

    // loaders: 4 threads/row, 16B (8 halfs) each; same pattern for A and B
    const int l_row = tid >> 2;          // 0..63
    const int l_q   = tid & 3;
    const bool a_valid = (bm + l_row) < M;
    const __half* gA = Ain + (size_t)(bm + l_row) * K + l_q * 8;
    const __half* gB = Wt + (size_t)(bn + l_row) * K + l_q * 8;

    uint32_t sA_dst[STAGES], sB_dst[STAGES];
#pragma unroll
    for (int s = 0; s < STAGES; s++) {
        sA_dst[s] = sbase + (s * BUF_WORDS + l_row * RSW + l_q * 4) * 4;
        sB_dst[s] = sbase + (s * BUF_WORDS + A_WORDS + l_row * RSW + l_q * 4) * 4;
    }

    auto prefetch = [&](int kt, int stg) {
        int k0 = kt * BK;
        cp_async16(sA_dst[stg], gA + k0, a_valid);
        cp_async16(sB_dst[stg], gB + k0, 1);
        cp_commit();
    };

    float acc[4][4];
#pragma unroll
    for (int nt = 0; nt < 4; nt++)
#pragma unroll
        for (int v = 0; v < 4; v++) acc[nt][v] = 0.f;

    const int nk = K / BK;
    prefetch(0, 0);
    if (nk > 1) prefetch(1, 1);
    if (nk > 2) prefetch(2, 2);

    for (int kt = 0; kt < nk; kt++) {
        if (kt + 2 < nk)      cp_wait2();
        else if (kt + 1 < nk) cp_wait1();
        else                  cp_wait0();
        __syncthreads();
        if (kt + 3 < nk) prefetch(kt + 3, (kt + 3) & (STAGES - 1));

        const int stg = kt & (STAGES - 1);
        const uint32_t* wA = smw + stg * BUF_WORDS + (warp_m * 16) * RSW;
        const uint32_t* wB = smw + stg * BUF_WORDS + A_WORDS + (warp_n * 32) * RSW;
#pragma unroll
        for (int ch = 0; ch < 2; ch++) {          // two K=16 chunks per stage
            uint2 af0 = *reinterpret_cast<const uint2*>(wA + r * RSW + ch * 8 + c * 2);
            uint2 af1 = *reinterpret_cast<const uint2*>(wA + (8 + r) * RSW + ch * 8 + c * 2);
            uint2 bf[4];
#pragma unroll
            for (int nt = 0; nt < 4; nt++)
                bf[nt] = *reinterpret_cast<const uint2*>(wB + (nt * 8 + r) * RSW + ch * 8 + c * 2);
#pragma unroll
            for (int nt = 0; nt < 4; nt++) {
                float* d = acc[nt];
                asm volatile(
                    "mma.sync.aligned.m16n8k16.row.col.f32.f16.f16.f32 "
                    "{%0,%1,%2,%3}, {%4,%5,%6,%7}, {%8,%9}, {%0,%1,%2,%3};"
                    : "+f"(d[0]), "+f"(d[1]), "+f"(d[2]), "+f"(d[3])
                    : "r"(af0.x), "r"(af1.x), "r"(af0.y), "r"(af1.y),
                      "r"(bf[nt].x), "r"(bf[nt].y));
            }
        }
    }
    __syncthreads();

    // ---- epilogue ----
#pragma unroll
    for (int h = 0; h < 2; h++) {
        int row = bm + warp_m * 16 + h * 8 + r;
        if (row >= M) continue;
        const __half* rp = (mode == 1) ? res + (size_t)row * DA : nullptr;
#pragma unroll
        for (int nt = 0; nt < 4; nt++) {
            int col = bn + warp_n * 32 + nt * 8 + c * 2;
            int pc = kp16(col);
            float v0 = silu(acc[nt][h * 2 + 0]);
            float v1 = silu(acc[nt][h * 2 + 1]);
            if (mode == 1) {
                float2 rv = __half22float2(
                    *reinterpret_cast<const __half2*>(rp + pc));
                v0 = (rv.x + v0) * INV_SQRT2;
                v1 = (rv.y + v1) * INV_SQRT2;
            }
            if (outf) {
                *reinterpret_cast<float2*>(outf + (size_t)row * DA + col) =
                    make_float2(v0, v1);
            } else {
                *reinterpret_cast<__half2*>(outh + (size_t)row * DA + pc) =
                    __floats2half2_rn(v0, v1);
            }
        }
    }
}

// ---------------- launch ----------------
extern "C" void kernel_launch(void* const* d_in, const int* in_sizes, int n_in,
                              void* d_out, int out_size) {
    // inputs: 0:h (unused), 1:m, 2:basis_rad, 3:idx_atom, 4:W_rbf, 5:W_in, 6:res_W1, 7:res_W2
    const float* m    = (const float*)d_in[1];
    const float* br   = (const float*)d_in[2];
    const int*   idx  = (const int*)d_in[3];
    const float* Wrbf = (const float*)d_in[4];
    const float* Win  = (const float*)d_in[5];
    const float* W1   = (const float*)d_in[6];
    const float* W2   = (const float*)d_in[7];
    float* out = (float*)d_out;

    int A  = in_sizes[0] / DA;           // 20000
    int E  = in_sizes[1] / DE;           // 250000
    int nh = in_sizes[6] / (DA * DA);    // 3
    if (A > NATOMS) A = NATOMS;
    if (E > NEDGES) E = NEDGES;

    __half *xbig, *xa, *ya, *wt;
    cudaGetSymbolAddress((void**)&xbig, g_xbig);
    cudaGetSymbolAddress((void**)&xa, g_xa);
    cudaGetSymbolAddress((void**)&ya, g_ya);
    cudaGetSymbolAddress((void**)&wt, g_wt);

    static bool attr_set = false;
    if (!attr_set) {
        cudaFuncSetAttribute(gemm_mma_kernel,
                             cudaFuncAttributeMaxDynamicSharedMemorySize, GEMM_SMEM);
        attr_set = true;
    }

    // counting sort (hist also zero-fills xbig)
    hist_kernel<<<(E + 255) / 256, 256>>>(idx, E, A);
    scan_kernel<<<1, 1024>>>(A, E);
    scatter_kernel<<<(E + 255) / 256, 256>>>(idx, E);

    // edge-parallel aggregation with tf32-mma rbf projection (4th launch -> ncu slot)
    aggregate_kernel<<<AGG_BLOCKS, 128>>>(m, br, Wrbf, idx, E, A);

    // all weight transposes in one launch
    transpose_all_kernel<<<592, 256>>>(Win, W1, W2, wt, nh);

    __half* wt0 = wt;  // W_in^T [256, 512]
    dim3 grid((A + 63) / 64, DA / 64);
    // x = silu(xbig @ W_in)
    gemm_mma_kernel<<<grid, 256, GEMM_SMEM>>>(xbig, wt0, nullptr, xa, nullptr, A, DE, 0);

    // residual layers
    for (int i = 0; i < nh; i++) {
        __half* w1t = wt + DA * DE + (size_t)(2 * i) * DA * DA;
        __half* w2t = wt + DA * DE + (size_t)(2 * i + 1) * DA * DA;
        gemm_mma_kernel<<<grid, 256, GEMM_SMEM>>>(xa, w1t, nullptr, ya, nullptr, A, DA, 0);
        if (i == nh - 1)
            gemm_mma_kernel<<<grid, 256, GEMM_SMEM>>>(ya, w2t, xa, nullptr, out, A, DA, 1);
        else
            gemm_mma_kernel<<<grid, 256, GEMM_SMEM>>>(ya, w2t, xa, xa, nullptr, A, DA, 1);
    }
}

// round 13
// speedup vs baseline: 1.0336x; 1.0336x over previous
#include <cuda_runtime.h>
#include <cuda_fp16.h>
#include <cstdint>
#include <math.h>

// Problem dims (fixed for this dataset)
#define NATOMS 20000
#define NEDGES 250000
#define DE 512
#define DA 256
#define DR 16

#define INV_SQRT2 0.70710678118654752440f

// fp16 k-permutation within each 16-element block:
// thread c's m16n8k16 fragment k's {2c,2c+1,2c+8,2c+9} land at {4c..4c+3}
__host__ __device__ __forceinline__ int kp16(int k) {
    int b = k & 15;
    return (k & ~15) | (b & 1) | (((b >> 1) & 3) << 2) | (((b >> 3) & 1) << 1);
}

// ---------------- scratch (device globals; no allocs allowed) ----------------
__device__ int    g_counts[NATOMS];          // zero at load; scan re-zeroes each pass
__device__ int    g_offsets[NATOMS + 1];
__device__ int    g_cursor[NATOMS];
__device__ int    g_sorted[NEDGES];
__device__ __half g_xbig[(size_t)NATOMS * DE];  // aggregated [A, De], fp16 kp-permuted
__device__ __half g_xa[(size_t)NATOMS * DA];    // atom features (fp16, kp-permuted)
__device__ __half g_ya[(size_t)NATOMS * DA];    // MLP intermediate (fp16, kp-permuted)
// transposed+fp16+kp-permuted weights: W_in^T [256,512] then 3x(W1^T,W2^T) [256,256]
__device__ __half g_wt[DA * DE + 6 * DA * DA];

// ---------------- helpers ----------------
__device__ __forceinline__ uint32_t smem_u32(const void* p) {
    uint32_t a;
    asm("{ .reg .u64 t; cvta.to.shared.u64 t, %1; cvt.u32.u64 %0, t; }" : "=r"(a) : "l"(p));
    return a;
}
__device__ __forceinline__ float silu(float x) { return x / (1.0f + __expf(-x)); }
__device__ __forceinline__ float tf32_rna(float x) {
    float y;
    asm("cvt.rna.tf32.f32 %0, %1;" : "=f"(y) : "f"(x));
    return y;
}

__device__ __forceinline__ void cp_async16(uint32_t dst, const void* src, int pred) {
    asm volatile("cp.async.cg.shared.global [%0], [%1], 16, %2;"
                 :: "r"(dst), "l"(src), "r"(pred ? 16 : 0) : "memory");
}
__device__ __forceinline__ void cp_commit() {
    asm volatile("cp.async.commit_group;" ::: "memory");
}
__device__ __forceinline__ void cp_wait0() {
    asm volatile("cp.async.wait_group 0;" ::: "memory");
}
__device__ __forceinline__ void cp_wait1() {
    asm volatile("cp.async.wait_group 1;" ::: "memory");
}
__device__ __forceinline__ void cp_wait2() {
    asm volatile("cp.async.wait_group 2;" ::: "memory");
}

// ---------------- counting sort of edges by atom ----------------
// hist also zero-fills g_xbig (0-edge atoms must read as zero)
__global__ void hist_kernel(const int* __restrict__ idx, int E, int A) {
    int i = blockIdx.x * blockDim.x + threadIdx.x;
    if (i < E) atomicAdd(&g_counts[idx[i]], 1);
    int total = A * DE / 8;   // uint4 = 8 halfs
    int nt = gridDim.x * blockDim.x;
    uint4 z = make_uint4(0u, 0u, 0u, 0u);
    uint4* px = reinterpret_cast<uint4*>(g_xbig);
    for (int j = i; j < total; j += nt) px[j] = z;
}
__global__ void scan_kernel(int A, int E) {
    __shared__ int sums[1024];
    int tid = threadIdx.x;
    int per = (A + 1023) / 1024;
    int start = tid * per;
    int end = min(start + per, A);
    int s = 0;
    for (int i = start; i < end; i++) s += g_counts[i];
    sums[tid] = s;
    __syncthreads();
    for (int off = 1; off < 1024; off <<= 1) {
        int v = 0;
        if (tid >= off) v = sums[tid - off];
        __syncthreads();
        sums[tid] += v;
        __syncthreads();
    }
    int run = (tid == 0) ? 0 : sums[tid - 1];
    for (int i = start; i < end; i++) {
        g_offsets[i] = run;
        g_cursor[i]  = run;
        run += g_counts[i];
        g_counts[i] = 0;
    }
    if (tid == 0) g_offsets[A] = E;
}
__global__ void scatter_kernel(const int* __restrict__ idx, int E) {
    int i = blockIdx.x * blockDim.x + threadIdx.x;
    if (i < E) {
        int p = atomicAdd(&g_cursor[idx[i]], 1);
        g_sorted[p] = i;
    }
}

// ---------------- edge-parallel aggregation: tf32-mma projection + 4-deep m pipeline ----------------
#define AGG_TILE 64
#define AGG_SUB 16
#define AGG_BLOCKS 740
#define BS_STRIDE 520     // floats per BS row (512 + 8 pad)

__global__ __launch_bounds__(128, 5)
void aggregate_kernel(const float* __restrict__ m,
                      const float* __restrict__ br,
                      const float* __restrict__ Wrbf,
                      const int* __restrict__ idx, int E, int A) {
    __shared__ float s_bs[AGG_SUB * BS_STRIDE];   // 33280 B
    __shared__ float s_br[AGG_TILE][16];
    __shared__ int   s_e[AGG_TILE];
    __shared__ int   s_atom[AGG_TILE];
    __shared__ int   s_ab[2];

    const int tid  = threadIdx.x;
    const int lane = tid & 31;
    const int wid  = tid >> 5;          // 0..3
    const int r    = lane >> 2;         // 0..7
    const int c    = lane & 3;          // 0..3
    const int wbase = wid * 128;        // this warp's 128 columns

    // Preload W_rbf B-fragments (tf32): 16 n-tiles x 2 k-chunks for this warp.
    uint32_t bw[16][2][2];
#pragma unroll
    for (int j = 0; j < 16; j++) {
#pragma unroll
        for (int kq = 0; kq < 2; kq++) {
            int col = wbase + j * 8 + r;
            bw[j][kq][0] = __float_as_uint(tf32_rna(Wrbf[(kq * 8 + c) * DE + col]));
            bw[j][kq][1] = __float_as_uint(tf32_rna(Wrbf[(kq * 8 + c + 4) * DE + col]));
        }
    }

    const int c0 = tid * 4;             // consume columns 4t..4t+3
    const int P01 = kp16(c0);           // fp16 store slot of cols {c0, c0+1}
    const int P23 = kp16(c0 + 2);

    const int epb = (E + gridDim.x - 1) / gridDim.x;
    if (tid < 2) {
        int target = min((int)(blockIdx.x + tid) * epb, E);
        int lo = 0, hi = A;
        while (lo < hi) {
            int mid = (lo + hi) >> 1;
            if (g_offsets[mid] >= target) hi = mid; else lo = mid + 1;
        }
        s_ab[tid] = lo;
    }
    __syncthreads();
    const int a_beg = s_ab[0], a_end = s_ab[1];
    if (a_beg >= a_end) return;
    const int j0 = g_offsets[a_beg];
    const int j1 = g_offsets[a_end];

    float4 acc = make_float4(0.f, 0.f, 0.f, 0.f);
    int cur_atom = -1;

    auto flush = [&](int a) {
        __half* p = g_xbig + (size_t)a * DE;
        *reinterpret_cast<__half2*>(p + P01) = __floats2half2_rn(acc.x, acc.y);
        *reinterpret_cast<__half2*>(p + P23) = __floats2half2_rn(acc.z, acc.w);
    };

    for (int t0 = j0; t0 < j1; t0 += AGG_TILE) {
        const int n = min(AGG_TILE, j1 - t0);
        __syncthreads();
        {   // stage basis rows (tf32-rounded) + edge ids + atom ids: 2 threads/edge
            int el = tid >> 1;
            int half_ = tid & 1;
            if (el < n) {
                int e = g_sorted[t0 + el];
                if (half_ == 0) { s_e[el] = e; s_atom[el] = idx[e]; }
                const float* bp = br + (size_t)e * DR + half_ * 8;
#pragma unroll
                for (int q = 0; q < 8; q++)
                    s_br[el][half_ * 8 + q] = tf32_rna(bp[q]);
            }
        }
        __syncthreads();

        // clamped m-row loader (spans sub-tile boundaries; clamp keeps it branch-free)
        auto ld_m = [&](int j) {
            int jj = j < n ? j : n - 1;
            return *reinterpret_cast<const float4*>(m + (size_t)s_e[jj] * DE + c0);
        };
        auto consume = [&](float4 mv, int gi, int li) {
            int a = s_atom[gi];
            if (a != cur_atom) {
                if (cur_atom >= 0) flush(cur_atom);
                cur_atom = a;
                acc = make_float4(0.f, 0.f, 0.f, 0.f);
            }
            float4 bs = *reinterpret_cast<const float4*>(&s_bs[li * BS_STRIDE + c0]);
            acc.x = fmaf(mv.x, bs.x, acc.x);
            acc.y = fmaf(mv.y, bs.y, acc.y);
            acc.z = fmaf(mv.z, bs.z, acc.z);
            acc.w = fmaf(mv.w, bs.w, acc.w);
        };

        // 4-deep register pipeline across the whole 64-edge tile
        float4 p0 = ld_m(0), p1 = ld_m(1), p2 = ld_m(2), p3 = ld_m(3);

        for (int st = 0; st < AGG_TILE / AGG_SUB; st++) {
            const int sb = st * AGG_SUB;
            if (sb >= n) break;
            const int n_sub = min(AGG_SUB, n - sb);

            // ---- mma phase: BS[0..15][wbase..wbase+127] ----
            uint32_t a0[2], a1[2], a2[2], a3[2];
#pragma unroll
            for (int kq = 0; kq < 2; kq++) {
                a0[kq] = __float_as_uint(s_br[sb + r][kq * 8 + c]);
                a1[kq] = __float_as_uint(s_br[sb + 8 + r][kq * 8 + c]);
                a2[kq] = __float_as_uint(s_br[sb + r][kq * 8 + c + 4]);
                a3[kq] = __float_as_uint(s_br[sb + 8 + r][kq * 8 + c + 4]);
            }
#pragma unroll
            for (int j = 0; j < 16; j++) {
                float d0 = 0.f, d1 = 0.f, d2 = 0.f, d3 = 0.f;
#pragma unroll
                for (int kq = 0; kq < 2; kq++) {
                    asm volatile(
                        "mma.sync.aligned.m16n8k8.row.col.f32.tf32.tf32.f32 "
                        "{%0,%1,%2,%3}, {%4,%5,%6,%7}, {%8,%9}, {%0,%1,%2,%3};"
                        : "+f"(d0), "+f"(d1), "+f"(d2), "+f"(d3)
                        : "r"(a0[kq]), "r"(a1[kq]), "r"(a2[kq]), "r"(a3[kq]),
                          "r"(bw[j][kq][0]), "r"(bw[j][kq][1]));
                }
                int colb = wbase + j * 8 + 2 * c;
                *reinterpret_cast<float2*>(&s_bs[r * BS_STRIDE + colb]) =
                    make_float2(d0, d1);
                *reinterpret_cast<float2*>(&s_bs[(r + 8) * BS_STRIDE + colb]) =
                    make_float2(d2, d3);
            }
            __syncwarp();   // warp's own STS -> LDS (cols match warp-local threads)

            // ---- consume with 4-deep refill ----
            int i = 0;
            for (; i + 4 <= n_sub; i += 4) {
                int gi = sb + i;
                consume(p0, gi,     i);     p0 = ld_m(gi + 4);
                consume(p1, gi + 1, i + 1); p1 = ld_m(gi + 5);
                consume(p2, gi + 2, i + 2); p2 = ld_m(gi + 6);
                consume(p3, gi + 3, i + 3); p3 = ld_m(gi + 7);
            }
            for (; i < n_sub; i++) {        // tail (<4): rotate
                consume(p0, sb + i, i);
                p0 = p1; p1 = p2; p2 = p3; p3 = ld_m(sb + i + 4);
            }
            __syncwarp();   // all lanes done reading s_bs before next mma overwrites
        }
    }
    if (cur_atom >= 0) flush(cur_atom);
}

// ---------------- all-weights transpose + fp16 convert + kp-permute ----------------
__global__ void transpose_all_kernel(const float* __restrict__ Win,
                                     const float* __restrict__ W1,
                                     const float* __restrict__ W2,
                                     __half* __restrict__ wt, int nh) {
    int total = DE * DA + 2 * nh * DA * DA;
    for (int i = blockIdx.x * blockDim.x + threadIdx.x; i < total;
         i += gridDim.x * blockDim.x) {
        const float* src;
        __half* dst;
        int K, rem;
        if (i < DE * DA) {
            src = Win; dst = wt; K = DE; rem = i;
        } else {
            int j = i - DE * DA;
            int t = j / (DA * DA);
            rem = j % (DA * DA);
            src = ((t & 1) == 0 ? W1 : W2) + (size_t)(t >> 1) * DA * DA;
            dst = wt + DE * DA + (size_t)t * DA * DA;
            K = DA;
        }
        int k = rem / DA, n = rem % DA;
        dst[(size_t)n * K + kp16(k)] = __float2half_rn(src[rem]);
    }
}

// ---------------- mma.sync fp16 GEMM: 64x64 tile, 256 thr, 4 CTAs/SM, 4-stage ----------------
#define BK 32                // fp16 elements of K per stage
#define RSW 24               // b32 words per smem row (48 halfs = 96B; conflict-free)
#define A_WORDS (64 * RSW)
#define B_WORDS (64 * RSW)
#define BUF_WORDS (A_WORDS + B_WORDS)
#define STAGES 4
#define GEMM_SMEM (STAGES * BUF_WORDS * 4)   // 49152 B

__global__ __launch_bounds__(256, 4)
void gemm_mma_kernel(const __half* __restrict__ Ain, const __half* __restrict__ Wt,
                     const __half* __restrict__ res, __half* __restrict__ outh,
                     float* __restrict__ outf, int M, int K, int mode) {
    extern __shared__ uint32_t smw[];
    const uint32_t sbase = smem_u32(smw);

    const int tid = threadIdx.x;
    const int lane = tid & 31;
    const int wid = tid >> 5;            // 0..7
    const int warp_m = wid & 3;          // 4 x 16 rows
    const int warp_n = wid >> 2;         // 2 x 32 cols
    const int bm = blockIdx.x * 64;
    const int bn = blockIdx.y * 64;
    const int r = lane >> 2;
    const int c = lane & 3;

    const int l_row = tid >> 2;          // 0..63
    const int l_q   = tid & 3;
    const bool a_valid = (bm + l_row) < M;
    const __half* gA = Ain + (size_t)(bm + l_row) * K + l_q * 8;
    const __half* gB = Wt + (size_t)(bn + l_row) * K + l_q * 8;

    uint32_t sA_dst[STAGES], sB_dst[STAGES];
#pragma unroll
    for (int s = 0; s < STAGES; s++) {
        sA_dst[s] = sbase + (s * BUF_WORDS + l_row * RSW + l_q * 4) * 4;
        sB_dst[s] = sbase + (s * BUF_WORDS + A_WORDS + l_row * RSW + l_q * 4) * 4;
    }

    auto prefetch = [&](int kt, int stg) {
        int k0 = kt * BK;
        cp_async16(sA_dst[stg], gA + k0, a_valid);
        cp_async16(sB_dst[stg], gB + k0, 1);
        cp_commit();
    };

    float acc[4][4];
#pragma unroll
    for (int nt = 0; nt < 4; nt++)
#pragma unroll
        for (int v = 0; v < 4; v++) acc[nt][v] = 0.f;

    const int nk = K / BK;
    prefetch(0, 0);
    if (nk > 1) prefetch(1, 1);
    if (nk > 2) prefetch(2, 2);

    for (int kt = 0; kt < nk; kt++) {
        if (kt + 2 < nk)      cp_wait2();
        else if (kt + 1 < nk) cp_wait1();
        else                  cp_wait0();
        __syncthreads();
        if (kt + 3 < nk) prefetch(kt + 3, (kt + 3) & (STAGES - 1));

        const int stg = kt & (STAGES - 1);
        const uint32_t* wA = smw + stg * BUF_WORDS + (warp_m * 16) * RSW;
        const uint32_t* wB = smw + stg * BUF_WORDS + A_WORDS + (warp_n * 32) * RSW;
#pragma unroll
        for (int ch = 0; ch < 2; ch++) {          // two K=16 chunks per stage
            uint2 af0 = *reinterpret_cast<const uint2*>(wA + r * RSW + ch * 8 + c * 2);
            uint2 af1 = *reinterpret_cast<const uint2*>(wA + (8 + r) * RSW + ch * 8 + c * 2);
            uint2 bf[4];
#pragma unroll
            for (int nt = 0; nt < 4; nt++)
                bf[nt] = *reinterpret_cast<const uint2*>(wB + (nt * 8 + r) * RSW + ch * 8 + c * 2);
#pragma unroll
            for (int nt = 0; nt < 4; nt++) {
                float* d = acc[nt];
                asm volatile(
                    "mma.sync.aligned.m16n8k16.row.col.f32.f16.f16.f32 "
                    "{%0,%1,%2,%3}, {%4,%5,%6,%7}, {%8,%9}, {%0,%1,%2,%3};"
                    : "+f"(d[0]), "+f"(d[1]), "+f"(d[2]), "+f"(d[3])
                    : "r"(af0.x), "r"(af1.x), "r"(af0.y), "r"(af1.y),
                      "r"(bf[nt].x), "r"(bf[nt].y));
            }
        }
    }
    __syncthreads();

    // ---- epilogue ----
#pragma unroll
    for (int h = 0; h < 2; h++) {
        int row = bm + warp_m * 16 + h * 8 + r;
        if (row >= M) continue;
        const __half* rp = (mode == 1) ? res + (size_t)row * DA : nullptr;
#pragma unroll
        for (int nt = 0; nt < 4; nt++) {
            int col = bn + warp_n * 32 + nt * 8 + c * 2;
            int pc = kp16(col);
            float v0 = silu(acc[nt][h * 2 + 0]);
            float v1 = silu(acc[nt][h * 2 + 1]);
            if (mode == 1) {
                float2 rv = __half22float2(
                    *reinterpret_cast<const __half2*>(rp + pc));
                v0 = (rv.x + v0) * INV_SQRT2;
                v1 = (rv.y + v1) * INV_SQRT2;
            }
            if (outf) {
                *reinterpret_cast<float2*>(outf + (size_t)row * DA + col) =
                    make_float2(v0, v1);
            } else {
                *reinterpret_cast<__half2*>(outh + (size_t)row * DA + pc) =
                    __floats2half2_rn(v0, v1);
            }
        }
    }
}

// ---------------- launch ----------------
extern "C" void kernel_launch(void* const* d_in, const int* in_sizes, int n_in,
                              void* d_out, int out_size) {
    // inputs: 0:h (unused), 1:m, 2:basis_rad, 3:idx_atom, 4:W_rbf, 5:W_in, 6:res_W1, 7:res_W2
    const float* m    = (const float*)d_in[1];
    const float* br   = (const float*)d_in[2];
    const int*   idx  = (const int*)d_in[3];
    const float* Wrbf = (const float*)d_in[4];
    const float* Win  = (const float*)d_in[5];
    const float* W1   = (const float*)d_in[6];
    const float* W2   = (const float*)d_in[7];
    float* out = (float*)d_out;

    int A  = in_sizes[0] / DA;           // 20000
    int E  = in_sizes[1] / DE;           // 250000
    int nh = in_sizes[6] / (DA * DA);    // 3
    if (A > NATOMS) A = NATOMS;
    if (E > NEDGES) E = NEDGES;

    __half *xbig, *xa, *ya, *wt;
    cudaGetSymbolAddress((void**)&xbig, g_xbig);
    cudaGetSymbolAddress((void**)&xa, g_xa);
    cudaGetSymbolAddress((void**)&ya, g_ya);
    cudaGetSymbolAddress((void**)&wt, g_wt);

    static bool attr_set = false;
    if (!attr_set) {
        cudaFuncSetAttribute(gemm_mma_kernel,
                             cudaFuncAttributeMaxDynamicSharedMemorySize, GEMM_SMEM);
        attr_set = true;
    }

    // counting sort (hist also zero-fills xbig)
    hist_kernel<<<(E + 255) / 256, 256>>>(idx, E, A);
    scan_kernel<<<1, 1024>>>(A, E);
    scatter_kernel<<<(E + 255) / 256, 256>>>(idx, E);

    // edge-parallel aggregation (4th launch -> ncu capture slot)
    aggregate_kernel<<<AGG_BLOCKS, 128>>>(m, br, Wrbf, idx, E, A);

    // all weight transposes in one launch
    transpose_all_kernel<<<592, 256>>>(Win, W1, W2, wt, nh);

    __half* wt0 = wt;  // W_in^T [256, 512]
    dim3 grid((A + 63) / 64, DA / 64);
    // x = silu(xbig @ W_in)
    gemm_mma_kernel<<<grid, 256, GEMM_SMEM>>>(xbig, wt0, nullptr, xa, nullptr, A, DE, 0);

    // residual layers
    for (int i = 0; i < nh; i++) {
        __half* w1t = wt + DA * DE + (size_t)(2 * i) * DA * DA;
        __half* w2t = wt + DA * DE + (size_t)(2 * i + 1) * DA * DA;
        gemm_mma_kernel<<<grid, 256, GEMM_SMEM>>>(xa, w1t, nullptr, ya, nullptr, A, DA, 0);
        if (i == nh - 1)
            gemm_mma_kernel<<<grid, 256, GEMM_SMEM>>>(ya, w2t, xa, nullptr, out, A, DA, 1);
        else
            gemm_mma_kernel<<<grid, 256, GEMM_SMEM>>>(ya, w2t, xa, xa, nullptr, A, DA, 1);
    }
}

// round 14
// speedup vs baseline: 1.0903x; 1.0549x over previous
#include <cuda_runtime.h>
#include <cuda_fp16.h>
#include <cstdint>
#include <math.h>

// Problem dims (fixed for this dataset)
#define NATOMS 20000
#define NEDGES 250000
#define DE 512
#define DA 256
#define DR 16

#define INV_SQRT2 0.70710678118654752440f

// fp16 k-permutation within each 16-element block:
// thread c's m16n8k16 fragment k's {2c,2c+1,2c+8,2c+9} land at {4c..4c+3}
__host__ __device__ __forceinline__ int kp16(int k) {
    int b = k & 15;
    return (k & ~15) | (b & 1) | (((b >> 1) & 3) << 2) | (((b >> 3) & 1) << 1);
}

// ---------------- scratch (device globals; no allocs allowed) ----------------
__device__ int    g_counts[NATOMS];          // zero at load; scan re-zeroes each pass
__device__ int    g_offsets[NATOMS + 1];
__device__ int    g_cursor[NATOMS];
__device__ int    g_sorted[NEDGES];
__device__ __half g_xbig[(size_t)NATOMS * DE];  // aggregated [A, De], fp16 kp-permuted
__device__ __half g_xa[(size_t)NATOMS * DA];    // atom features (fp16, kp-permuted)
__device__ __half g_ya[(size_t)NATOMS * DA];    // MLP intermediate (fp16, kp-permuted)
// transposed+fp16+kp-permuted weights: W_in^T [256,512] then 3x(W1^T,W2^T) [256,256]
__device__ __half g_wt[DA * DE + 6 * DA * DA];

// ---------------- helpers ----------------
__device__ __forceinline__ uint32_t smem_u32(const void* p) {
    uint32_t a;
    asm("{ .reg .u64 t; cvta.to.shared.u64 t, %1; cvt.u32.u64 %0, t; }" : "=r"(a) : "l"(p));
    return a;
}
__device__ __forceinline__ float silu(float x) { return x / (1.0f + __expf(-x)); }
__device__ __forceinline__ float tf32_rna(float x) {
    float y;
    asm("cvt.rna.tf32.f32 %0, %1;" : "=f"(y) : "f"(x));
    return y;
}

__device__ __forceinline__ void cp_async16(uint32_t dst, const void* src, int pred) {
    asm volatile("cp.async.cg.shared.global [%0], [%1], 16, %2;"
                 :: "r"(dst), "l"(src), "r"(pred ? 16 : 0) : "memory");
}
__device__ __forceinline__ void cp_commit() {
    asm volatile("cp.async.commit_group;" ::: "memory");
}
__device__ __forceinline__ void cp_wait0() {
    asm volatile("cp.async.wait_group 0;" ::: "memory");
}
__device__ __forceinline__ void cp_wait1() {
    asm volatile("cp.async.wait_group 1;" ::: "memory");
}
__device__ __forceinline__ void cp_wait2() {
    asm volatile("cp.async.wait_group 2;" ::: "memory");
}

// ---------------- hist + xbig zero-fill + weight transpose (fused) ----------------
__global__ void hist_kernel(const int* __restrict__ idx, int E, int A,
                            const float* __restrict__ Win,
                            const float* __restrict__ W1,
                            const float* __restrict__ W2,
                            __half* __restrict__ wt, int nh) {
    int i = blockIdx.x * blockDim.x + threadIdx.x;
    int nt = gridDim.x * blockDim.x;
    if (i < E) atomicAdd(&g_counts[idx[i]], 1);
    // zero-fill xbig
    int total = A * DE / 8;   // uint4 = 8 halfs
    uint4 z = make_uint4(0u, 0u, 0u, 0u);
    uint4* px = reinterpret_cast<uint4*>(g_xbig);
    for (int j = i; j < total; j += nt) px[j] = z;
    // weight transpose + fp16 + kp-permute
    int wtotal = DE * DA + 2 * nh * DA * DA;
    for (int j = i; j < wtotal; j += nt) {
        const float* src;
        __half* dst;
        int K, rem;
        if (j < DE * DA) {
            src = Win; dst = wt; K = DE; rem = j;
        } else {
            int q = j - DE * DA;
            int t = q / (DA * DA);
            rem = q % (DA * DA);
            src = ((t & 1) == 0 ? W1 : W2) + (size_t)(t >> 1) * DA * DA;
            dst = wt + DE * DA + (size_t)t * DA * DA;
            K = DA;
        }
        int k = rem / DA, n = rem % DA;
        dst[(size_t)n * K + kp16(k)] = __float2half_rn(src[rem]);
    }
}
__global__ void scan_kernel(int A, int E) {
    __shared__ int sums[1024];
    int tid = threadIdx.x;
    int per = (A + 1023) / 1024;
    int start = tid * per;
    int end = min(start + per, A);
    int s = 0;
    for (int i = start; i < end; i++) s += g_counts[i];
    sums[tid] = s;
    __syncthreads();
    for (int off = 1; off < 1024; off <<= 1) {
        int v = 0;
        if (tid >= off) v = sums[tid - off];
        __syncthreads();
        sums[tid] += v;
        __syncthreads();
    }
    int run = (tid == 0) ? 0 : sums[tid - 1];
    for (int i = start; i < end; i++) {
        g_offsets[i] = run;
        g_cursor[i]  = run;
        run += g_counts[i];
        g_counts[i] = 0;
    }
    if (tid == 0) g_offsets[A] = E;
}
__global__ void scatter_kernel(const int* __restrict__ idx, int E) {
    int i = blockIdx.x * blockDim.x + threadIdx.x;
    if (i < E) {
        int p = atomicAdd(&g_cursor[idx[i]], 1);
        g_sorted[p] = i;
    }
}

// ---------------- edge-parallel aggregation: tf32-mma projection, 256 thr, 2 cols/thr ----------------
#define AGG_TILE 64
#define AGG_SUB 16
#define AGG_BLOCKS 740
#define BS_STRIDE 520     // floats per BS row (512 + 8 pad)

__global__ __launch_bounds__(256, 4)
void aggregate_kernel(const float* __restrict__ m,
                      const float* __restrict__ br,
                      const float* __restrict__ Wrbf,
                      const int* __restrict__ idx, int E, int A) {
    __shared__ float s_bs[AGG_SUB * BS_STRIDE];   // 33280 B
    __shared__ float s_br[AGG_TILE][16];
    __shared__ int   s_e[AGG_TILE];
    __shared__ int   s_atom[AGG_TILE];
    __shared__ int   s_ab[2];

    const int tid  = threadIdx.x;
    const int lane = tid & 31;
    const int wid  = tid >> 5;          // 0..7
    const int r    = lane >> 2;         // 0..7
    const int c    = lane & 3;          // 0..3
    const int wbase = wid * 64;         // this warp's 64 columns

    // Preload W_rbf B-fragments (tf32): 8 n-tiles x 2 k-chunks for this warp.
    uint32_t bw[8][2][2];
#pragma unroll
    for (int j = 0; j < 8; j++) {
#pragma unroll
        for (int kq = 0; kq < 2; kq++) {
            int col = wbase + j * 8 + r;
            bw[j][kq][0] = __float_as_uint(tf32_rna(Wrbf[(kq * 8 + c) * DE + col]));
            bw[j][kq][1] = __float_as_uint(tf32_rna(Wrbf[(kq * 8 + c + 4) * DE + col]));
        }
    }

    const int c0 = tid * 2;             // consume columns 2t, 2t+1
    const int P01 = kp16(c0);           // consecutive permuted slots for {c0, c0+1}

    const int epb = (E + gridDim.x - 1) / gridDim.x;
    if (tid < 2) {
        int target = min((int)(blockIdx.x + tid) * epb, E);
        int lo = 0, hi = A;
        while (lo < hi) {
            int mid = (lo + hi) >> 1;
            if (g_offsets[mid] >= target) hi = mid; else lo = mid + 1;
        }
        s_ab[tid] = lo;
    }
    __syncthreads();
    const int a_beg = s_ab[0], a_end = s_ab[1];
    if (a_beg >= a_end) return;
    const int j0 = g_offsets[a_beg];
    const int j1 = g_offsets[a_end];

    float2 acc = make_float2(0.f, 0.f);
    int cur_atom = -1;

    auto flush = [&](int a) {
        __half* p = g_xbig + (size_t)a * DE;
        *reinterpret_cast<__half2*>(p + P01) = __floats2half2_rn(acc.x, acc.y);
    };

    for (int t0 = j0; t0 < j1; t0 += AGG_TILE) {
        const int n = min(AGG_TILE, j1 - t0);
        __syncthreads();
        {   // stage basis rows (tf32-rounded) + edge ids + atom ids: 4 threads/edge
            int el = tid >> 2;
            int q  = tid & 3;
            if (el < n) {
                int e = g_sorted[t0 + el];
                if (q == 0) { s_e[el] = e; s_atom[el] = idx[e]; }
                const float* bp = br + (size_t)e * DR + q * 4;
#pragma unroll
                for (int v = 0; v < 4; v++)
                    s_br[el][q * 4 + v] = tf32_rna(bp[v]);
            }
        }
        __syncthreads();

        // clamped m-row loader (spans sub-tile boundaries; branch-free)
        auto ld_m = [&](int j) {
            int jj = j < n ? j : n - 1;
            return *reinterpret_cast<const float2*>(m + (size_t)s_e[jj] * DE + c0);
        };
        auto consume = [&](float2 mv, int gi, int li) {
            int a = s_atom[gi];
            if (a != cur_atom) {
                if (cur_atom >= 0) flush(cur_atom);
                cur_atom = a;
                acc = make_float2(0.f, 0.f);
            }
            float2 bs = *reinterpret_cast<const float2*>(&s_bs[li * BS_STRIDE + c0]);
            acc.x = fmaf(mv.x, bs.x, acc.x);
            acc.y = fmaf(mv.y, bs.y, acc.y);
        };

        // 4-deep register pipeline across the 64-edge tile
        float2 p0 = ld_m(0), p1 = ld_m(1), p2 = ld_m(2), p3 = ld_m(3);

        for (int st = 0; st < AGG_TILE / AGG_SUB; st++) {
            const int sb = st * AGG_SUB;
            if (sb >= n) break;
            const int n_sub = min(AGG_SUB, n - sb);

            // ---- mma phase: BS[0..15][wbase..wbase+63] ----
            uint32_t a0[2], a1[2], a2[2], a3[2];
#pragma unroll
            for (int kq = 0; kq < 2; kq++) {
                a0[kq] = __float_as_uint(s_br[sb + r][kq * 8 + c]);
                a1[kq] = __float_as_uint(s_br[sb + 8 + r][kq * 8 + c]);
                a2[kq] = __float_as_uint(s_br[sb + r][kq * 8 + c + 4]);
                a3[kq] = __float_as_uint(s_br[sb + 8 + r][kq * 8 + c + 4]);
            }
#pragma unroll
            for (int j = 0; j < 8; j++) {
                float d0 = 0.f, d1 = 0.f, d2 = 0.f, d3 = 0.f;
#pragma unroll
                for (int kq = 0; kq < 2; kq++) {
                    asm volatile(
                        "mma.sync.aligned.m16n8k8.row.col.f32.tf32.tf32.f32 "
                        "{%0,%1,%2,%3}, {%4,%5,%6,%7}, {%8,%9}, {%0,%1,%2,%3};"
                        : "+f"(d0), "+f"(d1), "+f"(d2), "+f"(d3)
                        : "r"(a0[kq]), "r"(a1[kq]), "r"(a2[kq]), "r"(a3[kq]),
                          "r"(bw[j][kq][0]), "r"(bw[j][kq][1]));
                }
                int colb = wbase + j * 8 + 2 * c;
                *reinterpret_cast<float2*>(&s_bs[r * BS_STRIDE + colb]) =
                    make_float2(d0, d1);
                *reinterpret_cast<float2*>(&s_bs[(r + 8) * BS_STRIDE + colb]) =
                    make_float2(d2, d3);
            }
            __syncwarp();   // warp's own STS -> LDS (cols match warp-local threads)

            // ---- consume with 4-deep refill ----
            int i = 0;
            for (; i + 4 <= n_sub; i += 4) {
                int gi = sb + i;
                consume(p0, gi,     i);     p0 = ld_m(gi + 4);
                consume(p1, gi + 1, i + 1); p1 = ld_m(gi + 5);
                consume(p2, gi + 2, i + 2); p2 = ld_m(gi + 6);
                consume(p3, gi + 3, i + 3); p3 = ld_m(gi + 7);
            }
            for (; i < n_sub; i++) {        // tail (<4): rotate
                consume(p0, sb + i, i);
                p0 = p1; p1 = p2; p2 = p3; p3 = ld_m(sb + i + 4);
            }
            __syncwarp();   // all lanes done reading s_bs before next mma overwrites
        }
    }
    if (cur_atom >= 0) flush(cur_atom);
}

// ---------------- mma.sync fp16 GEMM: 64x64 tile, 256 thr, 4 CTAs/SM, 4-stage ----------------
#define BK 32                // fp16 elements of K per stage
#define RSW 24               // b32 words per smem row (48 halfs = 96B; conflict-free)
#define A_WORDS (64 * RSW)
#define B_WORDS (64 * RSW)
#define BUF_WORDS (A_WORDS + B_WORDS)
#define STAGES 4
#define GEMM_SMEM (STAGES * BUF_WORDS * 4)   // 49152 B

__global__ __launch_bounds__(256, 4)
void gemm_mma_kernel(const __half* __restrict__ Ain, const __half* __restrict__ Wt,
                     const __half* __restrict__ res, __half* __restrict__ outh,
                     float* __restrict__ outf, int M, int K, int mode) {
    extern __shared__ uint32_t smw[];
    const uint32_t sbase = smem_u32(smw);

    const int tid = threadIdx.x;
    const int lane = tid & 31;
    const int wid = tid >> 5;            // 0..7
    const int warp_m = wid & 3;          // 4 x 16 rows
    const int warp_n = wid >> 2;         // 2 x 32 cols
    const int bm = blockIdx.x * 64;
    const int bn = blockIdx.y * 64;
    const int r = lane >> 2;
    const int c = lane & 3;

    const int l_row = tid >> 2;          // 0..63
    const int l_q   = tid & 3;
    const bool a_valid = (bm + l_row) < M;
    const __half* gA = Ain + (size_t)(bm + l_row) * K + l_q * 8;
    const __half* gB = Wt + (size_t)(bn + l_row) * K + l_q * 8;

    uint32_t sA_dst[STAGES], sB_dst[STAGES];
#pragma unroll
    for (int s = 0; s < STAGES; s++) {
        sA_dst[s] = sbase + (s * BUF_WORDS + l_row * RSW + l_q * 4) * 4;
        sB_dst[s] = sbase + (s * BUF_WORDS + A_WORDS + l_row * RSW + l_q * 4) * 4;
    }

    auto prefetch = [&](int kt, int stg) {
        int k0 = kt * BK;
        cp_async16(sA_dst[stg], gA + k0, a_valid);
        cp_async16(sB_dst[stg], gB + k0, 1);
        cp_commit();
    };

    float acc[4][4];
#pragma unroll
    for (int nt = 0; nt < 4; nt++)
#pragma unroll
        for (int v = 0; v < 4; v++) acc[nt][v] = 0.f;

    const int nk = K / BK;
    prefetch(0, 0);
    if (nk > 1) prefetch(1, 1);
    if (nk > 2) prefetch(2, 2);

    for (int kt = 0; kt < nk; kt++) {
        if (kt + 2 < nk)      cp_wait2();
        else if (kt + 1 < nk) cp_wait1();
        else                  cp_wait0();
        __syncthreads();
        if (kt + 3 < nk) prefetch(kt + 3, (kt + 3) & (STAGES - 1));

        const int stg = kt & (STAGES - 1);
        const uint32_t* wA = smw + stg * BUF_WORDS + (warp_m * 16) * RSW;
        const uint32_t* wB = smw + stg * BUF_WORDS + A_WORDS + (warp_n * 32) * RSW;
#pragma unroll
        for (int ch = 0; ch < 2; ch++) {          // two K=16 chunks per stage
            uint2 af0 = *reinterpret_cast<const uint2*>(wA + r * RSW + ch * 8 + c * 2);
            uint2 af1 = *reinterpret_cast<const uint2*>(wA + (8 + r) * RSW + ch * 8 + c * 2);
            uint2 bf[4];
#pragma unroll
            for (int nt = 0; nt < 4; nt++)
                bf[nt] = *reinterpret_cast<const uint2*>(wB + (nt * 8 + r) * RSW + ch * 8 + c * 2);
#pragma unroll
            for (int nt = 0; nt < 4; nt++) {
                float* d = acc[nt];
                asm volatile(
                    "mma.sync.aligned.m16n8k16.row.col.f32.f16.f16.f32 "
                    "{%0,%1,%2,%3}, {%4,%5,%6,%7}, {%8,%9}, {%0,%1,%2,%3};"
                    : "+f"(d[0]), "+f"(d[1]), "+f"(d[2]), "+f"(d[3])
                    : "r"(af0.x), "r"(af1.x), "r"(af0.y), "r"(af1.y),
                      "r"(bf[nt].x), "r"(bf[nt].y));
            }
        }
    }
    __syncthreads();

    // ---- epilogue ----
#pragma unroll
    for (int h = 0; h < 2; h++) {
        int row = bm + warp_m * 16 + h * 8 + r;
        if (row >= M) continue;
        const __half* rp = (mode == 1) ? res + (size_t)row * DA : nullptr;
#pragma unroll
        for (int nt = 0; nt < 4; nt++) {
            int col = bn + warp_n * 32 + nt * 8 + c * 2;
            int pc = kp16(col);
            float v0 = silu(acc[nt][h * 2 + 0]);
            float v1 = silu(acc[nt][h * 2 + 1]);
            if (mode == 1) {
                float2 rv = __half22float2(
                    *reinterpret_cast<const __half2*>(rp + pc));
                v0 = (rv.x + v0) * INV_SQRT2;
                v1 = (rv.y + v1) * INV_SQRT2;
            }
            if (outf) {
                *reinterpret_cast<float2*>(outf + (size_t)row * DA + col) =
                    make_float2(v0, v1);
            } else {
                *reinterpret_cast<__half2*>(outh + (size_t)row * DA + pc) =
                    __floats2half2_rn(v0, v1);
            }
        }
    }
}

// ---------------- launch ----------------
extern "C" void kernel_launch(void* const* d_in, const int* in_sizes, int n_in,
                              void* d_out, int out_size) {
    // inputs: 0:h (unused), 1:m, 2:basis_rad, 3:idx_atom, 4:W_rbf, 5:W_in, 6:res_W1, 7:res_W2
    const float* m    = (const float*)d_in[1];
    const float* br   = (const float*)d_in[2];
    const int*   idx  = (const int*)d_in[3];
    const float* Wrbf = (const float*)d_in[4];
    const float* Win  = (const float*)d_in[5];
    const float* W1   = (const float*)d_in[6];
    const float* W2   = (const float*)d_in[7];
    float* out = (float*)d_out;

    int A  = in_sizes[0] / DA;           // 20000
    int E  = in_sizes[1] / DE;           // 250000
    int nh = in_sizes[6] / (DA * DA);    // 3
    if (A > NATOMS) A = NATOMS;
    if (E > NEDGES) E = NEDGES;

    __half *xbig, *xa, *ya, *wt;
    cudaGetSymbolAddress((void**)&xbig, g_xbig);
    cudaGetSymbolAddress((void**)&xa, g_xa);
    cudaGetSymbolAddress((void**)&ya, g_ya);
    cudaGetSymbolAddress((void**)&wt, g_wt);

    static bool attr_set = false;
    if (!attr_set) {
        cudaFuncSetAttribute(gemm_mma_kernel,
                             cudaFuncAttributeMaxDynamicSharedMemorySize, GEMM_SMEM);
        attr_set = true;
    }

    // hist + xbig zero-fill + weight transpose (fused)
    hist_kernel<<<(E + 255) / 256, 256>>>(idx, E, A, Win, W1, W2, wt, nh);
    scan_kernel<<<1, 1024>>>(A, E);
    scatter_kernel<<<(E + 255) / 256, 256>>>(idx, E);

    // edge-parallel aggregation (4th launch -> ncu capture slot)
    aggregate_kernel<<<AGG_BLOCKS, 256>>>(m, br, Wrbf, idx, E, A);

    __half* wt0 = wt;  // W_in^T [256, 512]
    dim3 grid((A + 63) / 64, DA / 64);
    // x = silu(xbig @ W_in)
    gemm_mma_kernel<<<grid, 256, GEMM_SMEM>>>(xbig, wt0, nullptr, xa, nullptr, A, DE, 0);

    // residual layers
    for (int i = 0; i < nh; i++) {
        __half* w1t = wt + DA * DE + (size_t)(2 * i) * DA * DA;
        __half* w2t = wt + DA * DE + (size_t)(2 * i + 1) * DA * DA;
        gemm_mma_kernel<<<grid, 256, GEMM_SMEM>>>(xa, w1t, nullptr, ya, nullptr, A, DA, 0);
        if (i == nh - 1)
            gemm_mma_kernel<<<grid, 256, GEMM_SMEM>>>(ya, w2t, xa, nullptr, out, A, DA, 1);
        else
            gemm_mma_kernel<<<grid, 256, GEMM_SMEM>>>(ya, w2t, xa, xa, nullptr, A, DA, 1);
    }
}

// round 15
// speedup vs baseline: 1.2734x; 1.1679x over previous
#include <cuda_runtime.h>
#include <cuda_fp16.h>
#include <cstdint>
#include <math.h>

// Problem dims (fixed for this dataset)
#define NATOMS 20000
#define NEDGES 250000
#define DE 512
#define DA 256
#define DR 16

#define INV_SQRT2 0.70710678118654752440f

// fp16 k-permutation within each 16-element block:
// thread c's m16n8k16 fragment k's {2c,2c+1,2c+8,2c+9} land at {4c..4c+3}
__host__ __device__ __forceinline__ int kp16(int k) {
    int b = k & 15;
    return (k & ~15) | (b & 1) | (((b >> 1) & 3) << 2) | (((b >> 3) & 1) << 1);
}

// ---------------- scratch (device globals; no allocs allowed) ----------------
__device__ int    g_counts[NATOMS];          // zero at load; scan re-zeroes each pass
__device__ int    g_offsets[NATOMS + 1];
__device__ int    g_cursor[NATOMS];
__device__ int    g_sorted[NEDGES];
__device__ __half g_xbig[(size_t)NATOMS * DE];  // aggregated [A, De], fp16 kp-permuted
__device__ __half g_xa[(size_t)NATOMS * DA];    // atom features (fp16, kp-permuted)
__device__ __half g_ya[(size_t)NATOMS * DA];    // MLP intermediate (fp16, kp-permuted)
// transposed+fp16+kp-permuted weights: W_in^T [256,512] then 3x(W1^T,W2^T) [256,256]
__device__ __half g_wt[DA * DE + 6 * DA * DA];

// ---------------- helpers ----------------
__device__ __forceinline__ uint32_t smem_u32(const void* p) {
    uint32_t a;
    asm("{ .reg .u64 t; cvta.to.shared.u64 t, %1; cvt.u32.u64 %0, t; }" : "=r"(a) : "l"(p));
    return a;
}
__device__ __forceinline__ float silu(float x) { return x / (1.0f + __expf(-x)); }
__device__ __forceinline__ float tf32_rna(float x) {
    float y;
    asm("cvt.rna.tf32.f32 %0, %1;" : "=f"(y) : "f"(x));
    return y;
}

__device__ __forceinline__ void cp_async16(uint32_t dst, const void* src, int pred) {
    asm volatile("cp.async.cg.shared.global [%0], [%1], 16, %2;"
                 :: "r"(dst), "l"(src), "r"(pred ? 16 : 0) : "memory");
}
__device__ __forceinline__ void cp_commit() {
    asm volatile("cp.async.commit_group;" ::: "memory");
}
__device__ __forceinline__ void cp_wait0() {
    asm volatile("cp.async.wait_group 0;" ::: "memory");
}
__device__ __forceinline__ void cp_wait1() {
    asm volatile("cp.async.wait_group 1;" ::: "memory");
}
__device__ __forceinline__ void cp_wait2() {
    asm volatile("cp.async.wait_group 2;" ::: "memory");
}

// ---------------- hist + xbig zero-fill + weight transpose (fused) ----------------
__global__ void hist_kernel(const int* __restrict__ idx, int E, int A,
                            const float* __restrict__ Win,
                            const float* __restrict__ W1,
                            const float* __restrict__ W2,
                            __half* __restrict__ wt, int nh) {
    int i = blockIdx.x * blockDim.x + threadIdx.x;
    int nt = gridDim.x * blockDim.x;
    if (i < E) atomicAdd(&g_counts[idx[i]], 1);
    // zero-fill xbig
    int total = A * DE / 8;   // uint4 = 8 halfs
    uint4 z = make_uint4(0u, 0u, 0u, 0u);
    uint4* px = reinterpret_cast<uint4*>(g_xbig);
    for (int j = i; j < total; j += nt) px[j] = z;
    // weight transpose + fp16 + kp-permute
    int wtotal = DE * DA + 2 * nh * DA * DA;
    for (int j = i; j < wtotal; j += nt) {
        const float* src;
        __half* dst;
        int K, rem;
        if (j < DE * DA) {
            src = Win; dst = wt; K = DE; rem = j;
        } else {
            int q = j - DE * DA;
            int t = q / (DA * DA);
            rem = q % (DA * DA);
            src = ((t & 1) == 0 ? W1 : W2) + (size_t)(t >> 1) * DA * DA;
            dst = wt + DE * DA + (size_t)t * DA * DA;
            K = DA;
        }
        int k = rem / DA, n = rem % DA;
        dst[(size_t)n * K + kp16(k)] = __float2half_rn(src[rem]);
    }
}
__global__ void scan_kernel(int A, int E) {
    __shared__ int sums[1024];
    int tid = threadIdx.x;
    int per = (A + 1023) / 1024;
    int start = tid * per;
    int end = min(start + per, A);
    int s = 0;
    for (int i = start; i < end; i++) s += g_counts[i];
    sums[tid] = s;
    __syncthreads();
    for (int off = 1; off < 1024; off <<= 1) {
        int v = 0;
        if (tid >= off) v = sums[tid - off];
        __syncthreads();
        sums[tid] += v;
        __syncthreads();
    }
    int run = (tid == 0) ? 0 : sums[tid - 1];
    for (int i = start; i < end; i++) {
        g_offsets[i] = run;
        g_cursor[i]  = run;
        run += g_counts[i];
        g_counts[i] = 0;
    }
    if (tid == 0) g_offsets[A] = E;
}
__global__ void scatter_kernel(const int* __restrict__ idx, int E) {
    int i = blockIdx.x * blockDim.x + threadIdx.x;
    if (i < E) {
        int p = atomicAdd(&g_cursor[idx[i]], 1);
        g_sorted[p] = i;
    }
}

// ---------------- edge-parallel aggregation: tf32-mma projection + 4-deep m pipeline ----------------
// (R13 configuration: 128 threads, 4 cols/thread, float4 m loads, 5 CTAs/SM)
#define AGG_TILE 64
#define AGG_SUB 16
#define AGG_BLOCKS 740
#define BS_STRIDE 520     // floats per BS row (512 + 8 pad)

__global__ __launch_bounds__(128, 5)
void aggregate_kernel(const float* __restrict__ m,
                      const float* __restrict__ br,
                      const float* __restrict__ Wrbf,
                      const int* __restrict__ idx, int E, int A) {
    __shared__ float s_bs[AGG_SUB * BS_STRIDE];   // 33280 B
    __shared__ float s_br[AGG_TILE][16];
    __shared__ int   s_e[AGG_TILE];
    __shared__ int   s_atom[AGG_TILE];
    __shared__ int   s_ab[2];

    const int tid  = threadIdx.x;
    const int lane = tid & 31;
    const int wid  = tid >> 5;          // 0..3
    const int r    = lane >> 2;         // 0..7
    const int c    = lane & 3;          // 0..3
    const int wbase = wid * 128;        // this warp's 128 columns

    // Preload W_rbf B-fragments (tf32): 16 n-tiles x 2 k-chunks for this warp.
    uint32_t bw[16][2][2];
#pragma unroll
    for (int j = 0; j < 16; j++) {
#pragma unroll
        for (int kq = 0; kq < 2; kq++) {
            int col = wbase + j * 8 + r;
            bw[j][kq][0] = __float_as_uint(tf32_rna(Wrbf[(kq * 8 + c) * DE + col]));
            bw[j][kq][1] = __float_as_uint(tf32_rna(Wrbf[(kq * 8 + c + 4) * DE + col]));
        }
    }

    const int c0 = tid * 4;             // consume columns 4t..4t+3
    const int P01 = kp16(c0);           // fp16 store slot of cols {c0, c0+1}
    const int P23 = kp16(c0 + 2);

    const int epb = (E + gridDim.x - 1) / gridDim.x;
    if (tid < 2) {
        int target = min((int)(blockIdx.x + tid) * epb, E);
        int lo = 0, hi = A;
        while (lo < hi) {
            int mid = (lo + hi) >> 1;
            if (g_offsets[mid] >= target) hi = mid; else lo = mid + 1;
        }
        s_ab[tid] = lo;
    }
    __syncthreads();
    const int a_beg = s_ab[0], a_end = s_ab[1];
    if (a_beg >= a_end) return;
    const int j0 = g_offsets[a_beg];
    const int j1 = g_offsets[a_end];

    float4 acc = make_float4(0.f, 0.f, 0.f, 0.f);
    int cur_atom = -1;

    auto flush = [&](int a) {
        __half* p = g_xbig + (size_t)a * DE;
        *reinterpret_cast<__half2*>(p + P01) = __floats2half2_rn(acc.x, acc.y);
        *reinterpret_cast<__half2*>(p + P23) = __floats2half2_rn(acc.z, acc.w);
    };

    for (int t0 = j0; t0 < j1; t0 += AGG_TILE) {
        const int n = min(AGG_TILE, j1 - t0);
        __syncthreads();
        {   // stage basis rows (tf32-rounded) + edge ids + atom ids: 2 threads/edge
            int el = tid >> 1;
            int half_ = tid & 1;
            if (el < n) {
                int e = g_sorted[t0 + el];
                if (half_ == 0) { s_e[el] = e; s_atom[el] = idx[e]; }
                const float* bp = br + (size_t)e * DR + half_ * 8;
#pragma unroll
                for (int q = 0; q < 8; q++)
                    s_br[el][half_ * 8 + q] = tf32_rna(bp[q]);
            }
        }
        __syncthreads();

        // clamped m-row loader (spans sub-tile boundaries; branch-free)
        auto ld_m = [&](int j) {
            int jj = j < n ? j : n - 1;
            return *reinterpret_cast<const float4*>(m + (size_t)s_e[jj] * DE + c0);
        };
        auto consume = [&](float4 mv, int gi, int li) {
            int a = s_atom[gi];
            if (a != cur_atom) {
                if (cur_atom >= 0) flush(cur_atom);
                cur_atom = a;
                acc = make_float4(0.f, 0.f, 0.f, 0.f);
            }
            float4 bs = *reinterpret_cast<const float4*>(&s_bs[li * BS_STRIDE + c0]);
            acc.x = fmaf(mv.x, bs.x, acc.x);
            acc.y = fmaf(mv.y, bs.y, acc.y);
            acc.z = fmaf(mv.z, bs.z, acc.z);
            acc.w = fmaf(mv.w, bs.w, acc.w);
        };

        // 4-deep register pipeline across the whole 64-edge tile
        float4 p0 = ld_m(0), p1 = ld_m(1), p2 = ld_m(2), p3 = ld_m(3);

        for (int st = 0; st < AGG_TILE / AGG_SUB; st++) {
            const int sb = st * AGG_SUB;
            if (sb >= n) break;
            const int n_sub = min(AGG_SUB, n - sb);

            // ---- mma phase: BS[0..15][wbase..wbase+127] ----
            uint32_t a0[2], a1[2], a2[2], a3[2];
#pragma unroll
            for (int kq = 0; kq < 2; kq++) {
                a0[kq] = __float_as_uint(s_br[sb + r][kq * 8 + c]);
                a1[kq] = __float_as_uint(s_br[sb + 8 + r][kq * 8 + c]);
                a2[kq] = __float_as_uint(s_br[sb + r][kq * 8 + c + 4]);
                a3[kq] = __float_as_uint(s_br[sb + 8 + r][kq * 8 + c + 4]);
            }
#pragma unroll
            for (int j = 0; j < 16; j++) {
                float d0 = 0.f, d1 = 0.f, d2 = 0.f, d3 = 0.f;
#pragma unroll
                for (int kq = 0; kq < 2; kq++) {
                    asm volatile(
                        "mma.sync.aligned.m16n8k8.row.col.f32.tf32.tf32.f32 "
                        "{%0,%1,%2,%3}, {%4,%5,%6,%7}, {%8,%9}, {%0,%1,%2,%3};"
                        : "+f"(d0), "+f"(d1), "+f"(d2), "+f"(d3)
                        : "r"(a0[kq]), "r"(a1[kq]), "r"(a2[kq]), "r"(a3[kq]),
                          "r"(bw[j][kq][0]), "r"(bw[j][kq][1]));
                }
                int colb = wbase + j * 8 + 2 * c;
                *reinterpret_cast<float2*>(&s_bs[r * BS_STRIDE + colb]) =
                    make_float2(d0, d1);
                *reinterpret_cast<float2*>(&s_bs[(r + 8) * BS_STRIDE + colb]) =
                    make_float2(d2, d3);
            }
            __syncwarp();   // warp's own STS -> LDS (cols match warp-local threads)

            // ---- consume with 4-deep refill ----
            int i = 0;
            for (; i + 4 <= n_sub; i += 4) {
                int gi = sb + i;
                consume(p0, gi,     i);     p0 = ld_m(gi + 4);
                consume(p1, gi + 1, i + 1); p1 = ld_m(gi + 5);
                consume(p2, gi + 2, i + 2); p2 = ld_m(gi + 6);
                consume(p3, gi + 3, i + 3); p3 = ld_m(gi + 7);
            }
            for (; i < n_sub; i++) {        // tail (<4): rotate
                consume(p0, sb + i, i);
                p0 = p1; p1 = p2; p2 = p3; p3 = ld_m(sb + i + 4);
            }
            __syncwarp();   // all lanes done reading s_bs before next mma overwrites
        }
    }
    if (cur_atom >= 0) flush(cur_atom);
}

// ---------------- mma.sync fp16 GEMM: 64x64 tile, 256 thr, 4 CTAs/SM, 4-stage ----------------
#define BK 32                // fp16 elements of K per stage
#define RSW 24               // b32 words per smem row (48 halfs = 96B; conflict-free)
#define A_WORDS (64 * RSW)
#define B_WORDS (64 * RSW)
#define BUF_WORDS (A_WORDS + B_WORDS)
#define STAGES 4
#define GEMM_SMEM (STAGES * BUF_WORDS * 4)   // 49152 B

__global__ __launch_bounds__(256, 4)
void gemm_mma_kernel(const __half* __restrict__ Ain, const __half* __restrict__ Wt,
                     const __half* __restrict__ res, __half* __restrict__ outh,
                     float* __restrict__ outf, int M, int K, int mode) {
    extern __shared__ uint32_t smw[];
    const uint32_t sbase = smem_u32(smw);

    const int tid = threadIdx.x;
    const int lane = tid & 31;
    const int wid = tid >> 5;            // 0..7
    const int warp_m = wid & 3;          // 4 x 16 rows
    const int warp_n = wid >> 2;         // 2 x 32 cols
    const int bm = blockIdx.x * 64;
    const int bn = blockIdx.y * 64;
    const int r = lane >> 2;
    const int c = lane & 3;

    const int l_row = tid >> 2;          // 0..63
    const int l_q   = tid & 3;
    const bool a_valid = (bm + l_row) < M;
    const __half* gA = Ain + (size_t)(bm + l_row) * K + l_q * 8;
    const __half* gB = Wt + (size_t)(bn + l_row) * K + l_q * 8;

    uint32_t sA_dst[STAGES], sB_dst[STAGES];
#pragma unroll
    for (int s = 0; s < STAGES; s++) {
        sA_dst[s] = sbase + (s * BUF_WORDS + l_row * RSW + l_q * 4) * 4;
        sB_dst[s] = sbase + (s * BUF_WORDS + A_WORDS + l_row * RSW + l_q * 4) * 4;
    }

    auto prefetch = [&](int kt, int stg) {
        int k0 = kt * BK;
        cp_async16(sA_dst[stg], gA + k0, a_valid);
        cp_async16(sB_dst[stg], gB + k0, 1);
        cp_commit();
    };

    float acc[4][4];
#pragma unroll
    for (int nt = 0; nt < 4; nt++)
#pragma unroll
        for (int v = 0; v < 4; v++) acc[nt][v] = 0.f;

    const int nk = K / BK;
    prefetch(0, 0);
    if (nk > 1) prefetch(1, 1);
    if (nk > 2) prefetch(2, 2);

    for (int kt = 0; kt < nk; kt++) {
        if (kt + 2 < nk)      cp_wait2();
        else if (kt + 1 < nk) cp_wait1();
        else                  cp_wait0();
        __syncthreads();
        if (kt + 3 < nk) prefetch(kt + 3, (kt + 3) & (STAGES - 1));

        const int stg = kt & (STAGES - 1);
        const uint32_t* wA = smw + stg * BUF_WORDS + (warp_m * 16) * RSW;
        const uint32_t* wB = smw + stg * BUF_WORDS + A_WORDS + (warp_n * 32) * RSW;
#pragma unroll
        for (int ch = 0; ch < 2; ch++) {          // two K=16 chunks per stage
            uint2 af0 = *reinterpret_cast<const uint2*>(wA + r * RSW + ch * 8 + c * 2);
            uint2 af1 = *reinterpret_cast<const uint2*>(wA + (8 + r) * RSW + ch * 8 + c * 2);
            uint2 bf[4];
#pragma unroll
            for (int nt = 0; nt < 4; nt++)
                bf[nt] = *reinterpret_cast<const uint2*>(wB + (nt * 8 + r) * RSW + ch * 8 + c * 2);
#pragma unroll
            for (int nt = 0; nt < 4; nt++) {
                float* d = acc[nt];
                asm volatile(
                    "mma.sync.aligned.m16n8k16.row.col.f32.f16.f16.f32 "
                    "{%0,%1,%2,%3}, {%4,%5,%6,%7}, {%8,%9}, {%0,%1,%2,%3};"
                    : "+f"(d[0]), "+f"(d[1]), "+f"(d[2]), "+f"(d[3])
                    : "r"(af0.x), "r"(af1.x), "r"(af0.y), "r"(af1.y),
                      "r"(bf[nt].x), "r"(bf[nt].y));
            }
        }
    }
    __syncthreads();

    // ---- epilogue ----
#pragma unroll
    for (int h = 0; h < 2; h++) {
        int row = bm + warp_m * 16 + h * 8 + r;
        if (row >= M) continue;
        const __half* rp = (mode == 1) ? res + (size_t)row * DA : nullptr;
#pragma unroll
        for (int nt = 0; nt < 4; nt++) {
            int col = bn + warp_n * 32 + nt * 8 + c * 2;
            int pc = kp16(col);
            float v0 = silu(acc[nt][h * 2 + 0]);
            float v1 = silu(acc[nt][h * 2 + 1]);
            if (mode == 1) {
                float2 rv = __half22float2(
                    *reinterpret_cast<const __half2*>(rp + pc));
                v0 = (rv.x + v0) * INV_SQRT2;
                v1 = (rv.y + v1) * INV_SQRT2;
            }
            if (outf) {
                *reinterpret_cast<float2*>(outf + (size_t)row * DA + col) =
                    make_float2(v0, v1);
            } else {
                *reinterpret_cast<__half2*>(outh + (size_t)row * DA + pc) =
                    __floats2half2_rn(v0, v1);
            }
        }
    }
}

// ---------------- launch ----------------
extern "C" void kernel_launch(void* const* d_in, const int* in_sizes, int n_in,
                              void* d_out, int out_size) {
    // inputs: 0:h (unused), 1:m, 2:basis_rad, 3:idx_atom, 4:W_rbf, 5:W_in, 6:res_W1, 7:res_W2
    const float* m    = (const float*)d_in[1];
    const float* br   = (const float*)d_in[2];
    const int*   idx  = (const int*)d_in[3];
    const float* Wrbf = (const float*)d_in[4];
    const float* Win  = (const float*)d_in[5];
    const float* W1   = (const float*)d_in[6];
    const float* W2   = (const float*)d_in[7];
    float* out = (float*)d_out;

    int A  = in_sizes[0] / DA;           // 20000
    int E  = in_sizes[1] / DE;           // 250000
    int nh = in_sizes[6] / (DA * DA);    // 3
    if (A > NATOMS) A = NATOMS;
    if (E > NEDGES) E = NEDGES;

    __half *xbig, *xa, *ya, *wt;
    cudaGetSymbolAddress((void**)&xbig, g_xbig);
    cudaGetSymbolAddress((void**)&xa, g_xa);
    cudaGetSymbolAddress((void**)&ya, g_ya);
    cudaGetSymbolAddress((void**)&wt, g_wt);

    static bool attr_set = false;
    if (!attr_set) {
        cudaFuncSetAttribute(gemm_mma_kernel,
                             cudaFuncAttributeMaxDynamicSharedMemorySize, GEMM_SMEM);
        attr_set = true;
    }

    // hist + xbig zero-fill + weight transpose (fused)
    hist_kernel<<<(E + 255) / 256, 256>>>(idx, E, A, Win, W1, W2, wt, nh);
    scan_kernel<<<1, 1024>>>(A, E);
    scatter_kernel<<<(E + 255) / 256, 256>>>(idx, E);

    // edge-parallel aggregation (4th launch -> ncu capture slot)
    aggregate_kernel<<<AGG_BLOCKS, 128>>>(m, br, Wrbf, idx, E, A);

    __half* wt0 = wt;  // W_in^T [256, 512]
    dim3 grid((A + 63) / 64, DA / 64);
    // x = silu(xbig @ W_in)
    gemm_mma_kernel<<<grid, 256, GEMM_SMEM>>>(xbig, wt0, nullptr, xa, nullptr, A, DE, 0);

    // residual layers
    for (int i = 0; i < nh; i++) {
        __half* w1t = wt + DA * DE + (size_t)(2 * i) * DA * DA;
        __half* w2t = wt + DA * DE + (size_t)(2 * i + 1) * DA * DA;
        gemm_mma_kernel<<<grid, 256, GEMM_SMEM>>>(xa, w1t, nullptr, ya, nullptr, A, DA, 0);
        if (i == nh - 1)
            gemm_mma_kernel<<<grid, 256, GEMM_SMEM>>>(ya, w2t, xa, nullptr, out, A, DA, 1);
        else
            gemm_mma_kernel<<<grid, 256, GEMM_SMEM>>>(ya, w2t, xa, xa, nullptr, A, DA, 1);
    }
}